// round 1
// baseline (speedup 1.0000x reference)
#include <cuda_runtime.h>
#include <math.h>
#include <stdint.h>

// Problem constants (fixed shapes)
#define B_   32
#define T_   2048
#define D_   512
#define H_   512
#define G4_  2048          // 4*H
#define NBLK 128           // recurrence blocks (<= 148 SMs -> all co-resident)
#define JPB  4             // h-indices per block (H / NBLK)
#define HS_STRIDE 516      // padded h row stride in smem (conflict-free float4)

// ---------------- device scratch (allocation-free rule: __device__ globals) ----
__device__ float g_xproj[(size_t)T_ * G4_ * B_];   // [t][g4][b]  (~512 MB)
__device__ __align__(16) float g_h[2][B_ * H_];    // double-buffered h, [b][j]
__device__ unsigned g_epoch;                       // bumped once per launch
__device__ volatile unsigned g_flags[NBLK];        // grid-barrier flags

// ---------------- epoch prologue (makes barrier flags monotonic across replays)
__global__ void lstm_epoch_kernel() {
    if (threadIdx.x == 0) g_epoch = g_epoch + 1u;
}

// ---------------- Phase 1: x_proj[t][g][b] = sum_d input[b][t][d]*W_ih[g][d] + b_ih[g] + b_hh[g]
// grid (T_, 16), 256 threads. Each block: one t, 128 gate rows, all 32 batches.
__global__ void __launch_bounds__(256) lstm_xproj_kernel(
    const float* __restrict__ input,
    const float* __restrict__ W_ih,
    const float* __restrict__ b_ih,
    const float* __restrict__ b_hh)
{
    __shared__ float xs[32][33];    // [k][b], padded
    __shared__ float ws[128][32];   // [g][k]

    const int t    = blockIdx.x;
    const int g0   = blockIdx.y * 128;
    const int tid  = threadIdx.x;
    const int lane = tid & 31;      // batch b
    const int wrow = tid >> 5;      // warp id 0..7 -> owns g rows wrow*16..+15

    float acc[16];
#pragma unroll
    for (int i = 0; i < 16; i++) acc[i] = 0.f;

    for (int kt = 0; kt < 16; kt++) {
        const int k0 = kt * 32;
        // stage x_t tile: input[b][t][k0+k] -> xs[k][b]   (coalesced over k)
        for (int i = tid; i < 1024; i += 256) {
            int b = i >> 5, k = i & 31;
            xs[k][b] = input[(size_t)b * (T_ * D_) + (size_t)t * D_ + k0 + k];
        }
        // stage W tile: W_ih[g0+g][k0+k] -> ws[g][k]      (coalesced over k)
        for (int i = tid; i < 4096; i += 256) {
            int g = i >> 5, k = i & 31;
            ws[g][k] = W_ih[(size_t)(g0 + g) * D_ + k0 + k];
        }
        __syncthreads();
#pragma unroll 4
        for (int k = 0; k < 32; k++) {
            float xv = xs[k][lane];              // conflict-free
#pragma unroll
            for (int gg = 0; gg < 16; gg++)      // ws broadcast within warp
                acc[gg] = fmaf(ws[wrow * 16 + gg][k], xv, acc[gg]);
        }
        __syncthreads();
    }
#pragma unroll
    for (int gg = 0; gg < 16; gg++) {
        int g = g0 + wrow * 16 + gg;
        // lanes over b -> fully coalesced stores
        g_xproj[((size_t)t * G4_ + g) * B_ + lane] = acc[gg] + b_ih[g] + b_hh[g];
    }
}

// ---------------- Phase 2: persistent recurrence kernel -----------------------
// 128 blocks x 512 threads. Block bid owns j in [bid*4, bid*4+4), all 4 gates,
// all 32 batches. W_hh slice (16 rows x 512) stays in SMEM for all 2048 steps.
// c-state never leaves the block (SMEM). h exchanged via L2 + flag barrier.
extern "C" __global__ void __launch_bounds__(512, 1) lstm_rec_kernel(
    const float* __restrict__ h0,
    const float* __restrict__ c0,
    const float* __restrict__ W_hh,
    float* __restrict__ out)
{
    extern __shared__ float smem[];
    float* hsmT = smem;                        // [32][HS_STRIDE]  h, [b][k]
    float* Wsm  = smem + 32 * HS_STRIDE;       // [16][512]        gate rows
    float* gacc = Wsm + 16 * 512;              // [16][32]         gate preacts
    float* csm  = gacc + 512;                  // [4][32]          cell state

    const int tid  = threadIdx.x;
    const int bid  = blockIdx.x;
    const int jg   = tid >> 5;                 // 0..15 = gate*4 + jloc
    const int b    = tid & 31;
    const int gate = jg >> 2;
    const int jloc = jg & 3;

    // load resident W_hh slice: row (gate*H + bid*4 + jloc), coalesced
    for (int i = tid; i < 16 * 512; i += 512) {
        int r = i >> 9, k = i & 511;
        int gt = r >> 2, jl = r & 3;
        Wsm[i] = W_hh[(size_t)(gt * H_ + bid * JPB + jl) * H_ + k];
    }
    // init c slice
    if (tid < 128) {
        int bb = tid & 31, jl = tid >> 5;
        csm[tid] = c0[bb * H_ + bid * JPB + jl];
    }
    const unsigned epoch = *((volatile unsigned*)&g_epoch);
    const unsigned base  = epoch * 4096u;      // step targets: base+1 .. base+2048
    __syncthreads();

    const float* wrowp = Wsm + jg * 512;
    const float* hrowp = hsmT + b * HS_STRIDE;

    for (int t = 0; t < T_; t++) {
        const float* hsrc = (t == 0) ? h0 : g_h[(t - 1) & 1];
        // stage full h [32][512] into smem (L2 reads, L1-bypassed)
        for (int i = tid; i < 4096; i += 512) {
            int bb = i >> 7, kc = i & 127;
            float4 v = __ldcg((const float4*)(hsrc + bb * H_ + kc * 4));
            *(float4*)(hsmT + bb * HS_STRIDE + kc * 4) = v;
        }
        // prefetch this thread's x_proj term early (DRAM latency hidden by GEMM)
        float xp = __ldcg(&g_xproj[((size_t)t * G4_ + gate * H_ + bid * JPB + jloc) * B_ + b]);
        __syncthreads();

        float acc = 0.f;
#pragma unroll 8
        for (int kc = 0; kc < 128; kc++) {
            float4 wv = *(const float4*)(wrowp + kc * 4);   // broadcast
            float4 hv = *(const float4*)(hrowp + kc * 4);   // conflict-free
            acc = fmaf(wv.x, hv.x, acc);
            acc = fmaf(wv.y, hv.y, acc);
            acc = fmaf(wv.z, hv.z, acc);
            acc = fmaf(wv.w, hv.w, acc);
        }
        gacc[jg * 32 + b] = acc + xp;
        __syncthreads();

        if (tid < 128) {
            int bb = tid & 31, jl = tid >> 5;
            float xi = gacc[(0 * 4 + jl) * 32 + bb];
            float xf = gacc[(1 * 4 + jl) * 32 + bb];
            float xg = gacc[(2 * 4 + jl) * 32 + bb];
            float xo = gacc[(3 * 4 + jl) * 32 + bb];
            float iv = 1.f / (1.f + expf(-xi));
            float fv = 1.f / (1.f + expf(-xf));
            float gv = tanhf(xg);
            float ov = 1.f / (1.f + expf(-xo));
            float c  = csm[tid];
            float cn = fv * c + iv * gv;
            float hn = ov * tanhf(cn);
            csm[tid] = cn;
            int j = bid * JPB + jl;
            __stcg(&g_h[t & 1][bb * H_ + j], hn);
            if (t == T_ - 1) {
                out[bb * H_ + j]            = hn;   // final h
                out[B_ * H_ + bb * H_ + j]  = cn;   // final c
            }
        }
        __syncthreads();

        // all-to-all flag barrier (monotonic targets across replays)
        const unsigned target = base + (unsigned)t + 1u;
        if (tid == 0) {
            __threadfence();                  // publish h writes before flag
            g_flags[bid] = target;            // volatile store
        }
        if (tid < NBLK) {
            while (g_flags[tid] < target) { } // volatile polls (L2)
            __threadfence();                  // acquire before reading new h
        }
        __syncthreads();
    }
}

// ---------------- launch ------------------------------------------------------
extern "C" void kernel_launch(void* const* d_in, const int* in_sizes, int n_in,
                              void* d_out, int out_size)
{
    const float* input = (const float*)d_in[0];
    const float* h0    = (const float*)d_in[1];
    const float* c0    = (const float*)d_in[2];
    const float* W_ih  = (const float*)d_in[3];
    const float* W_hh  = (const float*)d_in[4];
    const float* b_ih  = (const float*)d_in[5];
    const float* b_hh  = (const float*)d_in[6];
    float* out = (float*)d_out;

    // Phase 1: input projection for all timesteps
    dim3 grid1(T_, 16);
    lstm_xproj_kernel<<<grid1, 256>>>(input, W_ih, b_ih, b_hh);

    // epoch bump so the persistent kernel's barrier flags stay monotonic
    lstm_epoch_kernel<<<1, 1>>>();

    // Phase 2: persistent recurrence (needs >48KB dynamic smem)
    const int smem_bytes = (32 * HS_STRIDE + 16 * 512 + 512 + 128) * sizeof(float);
    cudaFuncSetAttribute(lstm_rec_kernel,
                         cudaFuncAttributeMaxDynamicSharedMemorySize, smem_bytes);
    lstm_rec_kernel<<<NBLK, 512, smem_bytes>>>(h0, c0, W_hh, out);
}

// round 4
// speedup vs baseline: 1.3466x; 1.3466x over previous
#include <cuda_runtime.h>
#include <math.h>
#include <stdint.h>

#define B_   32
#define T_   2048
#define D_   512
#define H_   512
#define G4_  2048
#define NBLK 128
#define WS_  513        // Wsm row stride (513 mod 32 == 1 -> conflict-free)
#define HS_  33         // hsm row stride: bank = k + const (conflict-free)
#define GA_  33
#define XS_  34

// ---------------- device scratch ----------------------------------------------
__device__ float g_xproj[(size_t)T_ * G4_ * B_];   // [t][g][b]
__device__ __align__(16) float g_h[2][H_ * B_];    // [j][b]  double-buffered
__device__ unsigned g_epoch;
__device__ volatile unsigned g_flags[NBLK];

// ---------------- f32x2 helpers ------------------------------------------------
__device__ __forceinline__ unsigned long long pack2(float lo, float hi) {
    unsigned long long r;
    asm("mov.b64 %0, {%1, %2};" : "=l"(r) : "f"(lo), "f"(hi));
    return r;
}
__device__ __forceinline__ void fma2(unsigned long long& d,
                                     unsigned long long a, unsigned long long b) {
    asm("fma.rn.f32x2 %0, %1, %2, %0;" : "+l"(d) : "l"(a), "l"(b));
}
__device__ __forceinline__ void unpack2(unsigned long long v, float& lo, float& hi) {
    asm("mov.b64 {%0, %1}, %2;" : "=f"(lo), "=f"(hi) : "l"(v));
}

__global__ void lstm_epoch_kernel() {
    if (threadIdx.x == 0) g_epoch = g_epoch + 1u;
}

// ---------------- Phase 1: x_proj ---------------------------------------------
// grid (T_,16), 128 threads. Thread (gg=tid>>3, bg=tid&7): rows g = gg+16i (i<8),
// batches b = bg*4..+3 (2 f32x2 pairs). FMA2-bound.
__global__ void __launch_bounds__(128, 4) lstm_xproj_kernel(
    const float* __restrict__ input,
    const float* __restrict__ W_ih,
    const float* __restrict__ b_ih,
    const float* __restrict__ b_hh)
{
    __shared__ float ws[128 * 36];   // [g][k], row stride 36 (16B-aligned rows)
    __shared__ float xs[32 * XS_];   // [k][b]

    const int t   = blockIdx.x;
    const int g0  = blockIdx.y * 128;
    const int tid = threadIdx.x;
    const int gg  = tid >> 3;
    const int bg  = tid & 7;

    unsigned long long acc2[16];
#pragma unroll
    for (int v = 0; v < 16; v++) acc2[v] = 0ull;

    for (int kt = 0; kt < 16; kt++) {
        const int k0 = kt * 32;
#pragma unroll
        for (int m = 0; m < 8; m++) {                  // W tile: 128g x 32k
            int f4 = tid + m * 128;
            int g = f4 >> 3, kq = f4 & 7;
            float4 v = *(const float4*)&W_ih[(size_t)(g0 + g) * D_ + k0 + kq * 4];
            *(float4*)&ws[g * 36 + kq * 4] = v;
        }
#pragma unroll
        for (int m = 0; m < 2; m++) {                  // x tile: 32b x 32k -> xs[k][b]
            int f4 = tid + m * 128;
            int b = f4 >> 3, kq = f4 & 7;
            float4 v = *(const float4*)&input[((size_t)b * T_ + t) * D_ + k0 + kq * 4];
            xs[(kq * 4 + 0) * XS_ + b] = v.x;
            xs[(kq * 4 + 1) * XS_ + b] = v.y;
            xs[(kq * 4 + 2) * XS_ + b] = v.z;
            xs[(kq * 4 + 3) * XS_ + b] = v.w;
        }
        __syncthreads();

#pragma unroll
        for (int k4 = 0; k4 < 8; k4++) {
            float4 wv[8];
#pragma unroll
            for (int i = 0; i < 8; i++)
                wv[i] = *(const float4*)&ws[(gg + 16 * i) * 36 + k4 * 4];
#pragma unroll
            for (int kk = 0; kk < 4; kk++) {
                const float* xrow = &xs[(k4 * 4 + kk) * XS_ + bg * 4];
                unsigned long long x2a = *(const unsigned long long*)(xrow);
                unsigned long long x2b = *(const unsigned long long*)(xrow + 2);
#pragma unroll
                for (int i = 0; i < 8; i++) {
                    float w = (kk == 0) ? wv[i].x : (kk == 1) ? wv[i].y
                             : (kk == 2) ? wv[i].z : wv[i].w;
                    unsigned long long w2 = pack2(w, w);
                    fma2(acc2[i * 2 + 0], w2, x2a);
                    fma2(acc2[i * 2 + 1], w2, x2b);
                }
            }
        }
        __syncthreads();
    }

#pragma unroll
    for (int i = 0; i < 8; i++) {
        int g = g0 + gg + 16 * i;
        float bias = b_ih[g] + b_hh[g];
        float4 o; float lo, hi;
        unpack2(acc2[i * 2 + 0], lo, hi); o.x = lo + bias; o.y = hi + bias;
        unpack2(acc2[i * 2 + 1], lo, hi); o.z = lo + bias; o.w = hi + bias;
        *(float4*)&g_xproj[((size_t)t * G4_ + g) * B_ + bg * 4] = o;
    }
}

// ---------------- Phase 2: persistent recurrence ------------------------------
// 128 blocks x 512 threads. Block owns 16 rows (4 gates x 4 j = bid*4..+3).
// Warp w: rg = w>>2 (rows rg+4i), bg = w&3 (b = bg*8+j). Lane = k-slice
// (k = lane+32kc). Partials reduced by compacted butterfly shuffle.
extern "C" __global__ void __launch_bounds__(512, 1) lstm_rec_kernel(
    const float* __restrict__ h0,
    const float* __restrict__ c0,
    const float* __restrict__ W_hh,
    float* __restrict__ out)
{
    extern __shared__ float smem[];
    float* Wsm  = smem;                        // [16][WS_]
    float* hsm  = Wsm + 16 * WS_;              // [512][HS_]  ([k][b])
    float* gacc = hsm + 512 * HS_;             // [16][GA_]
    float* csm  = gacc + 16 * GA_;             // [4][32]

    const int tid  = threadIdx.x;
    const int bid  = blockIdx.x;
    const int w    = tid >> 5;
    const int lane = tid & 31;
    const int rg   = w >> 2;
    const int bg   = w & 3;

    for (int i = tid; i < 16 * 512; i += 512) {
        int r = i >> 9, k = i & 511;
        int gt = r >> 2, jl = r & 3;
        Wsm[r * WS_ + k] = W_hh[(size_t)(gt * H_ + bid * 4 + jl) * H_ + k];
    }
    if (tid < 128) {
        int bb = tid & 31, jl = tid >> 5;
        csm[tid] = c0[bb * H_ + bid * 4 + jl];
    }
    const unsigned epoch = *((volatile unsigned*)&g_epoch);
    const unsigned base  = epoch * 4096u;

    const int r_out = rg + 4 * (lane >> 3);
    const int b_out = bg * 8 + (lane & 7);
    const int gate_out = r_out >> 2, jl_out = r_out & 3;
    const float* xp_base =
        &g_xproj[(size_t)(gate_out * H_ + bid * 4 + jl_out) * B_ + b_out];
    __syncthreads();

    for (int t = 0; t < T_; t++) {
        // ---- stage h into hsm[k][b] ----
        if (t == 0) {
#pragma unroll 4
            for (int m = 0; m < 32; m++) {
                int idx = m * 512 + tid;               // h0 is [b][k]
                int b = idx >> 9, k = idx & 511;
                hsm[k * HS_ + b] = h0[idx];
            }
        } else {
            const float* hsrc = g_h[(t - 1) & 1];      // [k][b] flat
#pragma unroll
            for (int m = 0; m < 8; m++) {
                int f4 = m * 512 + tid;
                float4 v = __ldcg((const float4*)(hsrc) + f4);
                int k = f4 >> 3, b = (f4 & 7) * 4;
                hsm[k * HS_ + b + 0] = v.x;
                hsm[k * HS_ + b + 1] = v.y;
                hsm[k * HS_ + b + 2] = v.z;
                hsm[k * HS_ + b + 3] = v.w;
            }
        }
        float xp = __ldcg(xp_base + (size_t)t * (G4_ * B_));
        __syncthreads();

        // ---- GEMM over this lane's k-slice ----
        unsigned long long acc2[16];
#pragma unroll
        for (int q = 0; q < 16; q++) acc2[q] = 0ull;

#pragma unroll 4
        for (int kc = 0; kc < 16; kc++) {
            const int k = lane + 32 * kc;
            float hF[8];
#pragma unroll
            for (int j = 0; j < 8; j++) hF[j] = hsm[k * HS_ + bg * 8 + j];
            unsigned long long h2[4];
#pragma unroll
            for (int jp = 0; jp < 4; jp++) h2[jp] = pack2(hF[2 * jp], hF[2 * jp + 1]);
#pragma unroll
            for (int i = 0; i < 4; i++) {
                float wv = Wsm[(rg + 4 * i) * WS_ + k];
                unsigned long long w2 = pack2(wv, wv);
#pragma unroll
                for (int jp = 0; jp < 4; jp++) fma2(acc2[i * 4 + jp], w2, h2[jp]);
            }
        }

        float v[32];
#pragma unroll
        for (int i = 0; i < 4; i++)
#pragma unroll
            for (int jp = 0; jp < 4; jp++) {
                float lo, hi;
                unpack2(acc2[i * 4 + jp], lo, hi);
                v[i * 8 + 2 * jp]     = lo;
                v[i * 8 + 2 * jp + 1] = hi;
            }

        // ---- compacted butterfly reduce: lane ends holding sum of v[lane] ----
#pragma unroll
        for (int s = 0; s < 16; s++) {
            float ta = __shfl_xor_sync(0xffffffffu, v[s], 16);
            float tb = __shfl_xor_sync(0xffffffffu, v[s + 16], 16);
            v[s] = (lane & 16) ? (v[s + 16] + tb) : (v[s] + ta);
        }
#pragma unroll
        for (int s = 0; s < 8; s++) {
            float ta = __shfl_xor_sync(0xffffffffu, v[s], 8);
            float tb = __shfl_xor_sync(0xffffffffu, v[s + 8], 8);
            v[s] = (lane & 8) ? (v[s + 8] + tb) : (v[s] + ta);
        }
#pragma unroll
        for (int s = 0; s < 4; s++) {
            float ta = __shfl_xor_sync(0xffffffffu, v[s], 4);
            float tb = __shfl_xor_sync(0xffffffffu, v[s + 4], 4);
            v[s] = (lane & 4) ? (v[s + 4] + tb) : (v[s] + ta);
        }
#pragma unroll
        for (int s = 0; s < 2; s++) {
            float ta = __shfl_xor_sync(0xffffffffu, v[s], 2);
            float tb = __shfl_xor_sync(0xffffffffu, v[s + 2], 2);
            v[s] = (lane & 2) ? (v[s + 2] + tb) : (v[s] + ta);
        }
        {
            float ta = __shfl_xor_sync(0xffffffffu, v[0], 1);
            float tb = __shfl_xor_sync(0xffffffffu, v[1], 1);
            v[0] = (lane & 1) ? (v[1] + tb) : (v[0] + ta);
        }
        gacc[r_out * GA_ + b_out] = v[0] + xp;
        __syncthreads();

        // ---- activations + state update ----
        if (tid < 128) {
            int bb = tid & 31, jl = tid >> 5;
            float xi = gacc[(0 * 4 + jl) * GA_ + bb];
            float xf = gacc[(1 * 4 + jl) * GA_ + bb];
            float xg = gacc[(2 * 4 + jl) * GA_ + bb];
            float xo = gacc[(3 * 4 + jl) * GA_ + bb];
            float iv = 1.f / (1.f + expf(-xi));
            float fv = 1.f / (1.f + expf(-xf));
            float gv = tanhf(xg);
            float ov = 1.f / (1.f + expf(-xo));
            float c  = csm[tid];
            float cn = fv * c + iv * gv;
            float hn = ov * tanhf(cn);
            csm[tid] = cn;
            int j = bid * 4 + jl;
            __stcg(&g_h[t & 1][j * B_ + bb], hn);      // [j][b]
            if (t == T_ - 1) {
                out[bb * H_ + j]           = hn;       // final h [b][j]
                out[B_ * H_ + bb * H_ + j] = cn;       // final c [b][j]
            }
        }
        __syncthreads();

        // ---- grid barrier (flag array, monotonic across replays) ----
        const unsigned target = base + (unsigned)t + 1u;
        if (tid == 0) {
            __threadfence();
            g_flags[bid] = target;
        }
        if (tid < NBLK) {
            while (g_flags[tid] < target) { }
            __threadfence();
        }
        __syncthreads();
    }
}

// ---------------- launch ------------------------------------------------------
extern "C" void kernel_launch(void* const* d_in, const int* in_sizes, int n_in,
                              void* d_out, int out_size)
{
    const float* input = (const float*)d_in[0];
    const float* h0    = (const float*)d_in[1];
    const float* c0    = (const float*)d_in[2];
    const float* W_ih  = (const float*)d_in[3];
    const float* W_hh  = (const float*)d_in[4];
    const float* b_ih  = (const float*)d_in[5];
    const float* b_hh  = (const float*)d_in[6];
    float* out = (float*)d_out;

    dim3 grid1(T_, 16);
    lstm_xproj_kernel<<<grid1, 128>>>(input, W_ih, b_ih, b_hh);

    lstm_epoch_kernel<<<1, 1>>>();

    const int smem_bytes = (16 * WS_ + 512 * HS_ + 16 * GA_ + 128) * sizeof(float);
    cudaFuncSetAttribute(lstm_rec_kernel,
                         cudaFuncAttributeMaxDynamicSharedMemorySize, smem_bytes);
    lstm_rec_kernel<<<NBLK, 512, smem_bytes>>>(h0, c0, W_hh, out);
}

// round 5
// speedup vs baseline: 1.4721x; 1.0931x over previous
#include <cuda_runtime.h>
#include <math.h>
#include <stdint.h>

#define B_   32
#define T_   2048
#define D_   512
#define H_   512
#define G4_  2048
#define NBLK 128
#define HS_  33         // hsm row stride: bank = k + const (conflict-free)
#define GA_  33
#define XS_  34

// ---------------- device scratch ----------------------------------------------
__device__ float g_xproj[(size_t)T_ * G4_ * B_];   // [t][g][b]
__device__ __align__(16) float g_h[2][H_ * B_];    // [j][b]  double-buffered
__device__ unsigned g_epoch;
__device__ unsigned g_flags[NBLK];

// ---------------- f32x2 + sync helpers -----------------------------------------
__device__ __forceinline__ unsigned long long pack2(float lo, float hi) {
    unsigned long long r;
    asm("mov.b64 %0, {%1, %2};" : "=l"(r) : "f"(lo), "f"(hi));
    return r;
}
__device__ __forceinline__ void fma2(unsigned long long& d,
                                     unsigned long long a, unsigned long long b) {
    asm("fma.rn.f32x2 %0, %1, %2, %0;" : "+l"(d) : "l"(a), "l"(b));
}
__device__ __forceinline__ void unpack2(unsigned long long v, float& lo, float& hi) {
    asm("mov.b64 {%0, %1}, %2;" : "=f"(lo), "=f"(hi) : "l"(v));
}
__device__ __forceinline__ unsigned ld_acq(const unsigned* p) {
    unsigned v;
    asm volatile("ld.acquire.gpu.u32 %0, [%1];" : "=r"(v) : "l"(p) : "memory");
    return v;
}
__device__ __forceinline__ void st_rel(unsigned* p, unsigned v) {
    asm volatile("st.release.gpu.u32 [%0], %1;" :: "l"(p), "r"(v) : "memory");
}
__device__ __forceinline__ float tanh_approx(float x) {
    float y;
    asm("tanh.approx.f32 %0, %1;" : "=f"(y) : "f"(x));
    return y;
}
__device__ __forceinline__ float sigmoid_fast(float x) {
    return fmaf(tanh_approx(0.5f * x), 0.5f, 0.5f);
}

__global__ void lstm_epoch_kernel() {
    if (threadIdx.x == 0) g_epoch = g_epoch + 1u;
}

// ---------------- Phase 1: x_proj (unchanged from R4) --------------------------
__global__ void __launch_bounds__(128, 4) lstm_xproj_kernel(
    const float* __restrict__ input,
    const float* __restrict__ W_ih,
    const float* __restrict__ b_ih,
    const float* __restrict__ b_hh)
{
    __shared__ float ws[128 * 36];
    __shared__ float xs[32 * XS_];

    const int t   = blockIdx.x;
    const int g0  = blockIdx.y * 128;
    const int tid = threadIdx.x;
    const int gg  = tid >> 3;
    const int bg  = tid & 7;

    unsigned long long acc2[16];
#pragma unroll
    for (int v = 0; v < 16; v++) acc2[v] = 0ull;

    for (int kt = 0; kt < 16; kt++) {
        const int k0 = kt * 32;
#pragma unroll
        for (int m = 0; m < 8; m++) {
            int f4 = tid + m * 128;
            int g = f4 >> 3, kq = f4 & 7;
            float4 v = *(const float4*)&W_ih[(size_t)(g0 + g) * D_ + k0 + kq * 4];
            *(float4*)&ws[g * 36 + kq * 4] = v;
        }
#pragma unroll
        for (int m = 0; m < 2; m++) {
            int f4 = tid + m * 128;
            int b = f4 >> 3, kq = f4 & 7;
            float4 v = *(const float4*)&input[((size_t)b * T_ + t) * D_ + k0 + kq * 4];
            xs[(kq * 4 + 0) * XS_ + b] = v.x;
            xs[(kq * 4 + 1) * XS_ + b] = v.y;
            xs[(kq * 4 + 2) * XS_ + b] = v.z;
            xs[(kq * 4 + 3) * XS_ + b] = v.w;
        }
        __syncthreads();

#pragma unroll
        for (int k4 = 0; k4 < 8; k4++) {
            float4 wv[8];
#pragma unroll
            for (int i = 0; i < 8; i++)
                wv[i] = *(const float4*)&ws[(gg + 16 * i) * 36 + k4 * 4];
#pragma unroll
            for (int kk = 0; kk < 4; kk++) {
                const float* xrow = &xs[(k4 * 4 + kk) * XS_ + bg * 4];
                unsigned long long x2a = *(const unsigned long long*)(xrow);
                unsigned long long x2b = *(const unsigned long long*)(xrow + 2);
#pragma unroll
                for (int i = 0; i < 8; i++) {
                    float w = (kk == 0) ? wv[i].x : (kk == 1) ? wv[i].y
                             : (kk == 2) ? wv[i].z : wv[i].w;
                    unsigned long long w2 = pack2(w, w);
                    fma2(acc2[i * 2 + 0], w2, x2a);
                    fma2(acc2[i * 2 + 1], w2, x2b);
                }
            }
        }
        __syncthreads();
    }

#pragma unroll
    for (int i = 0; i < 8; i++) {
        int g = g0 + gg + 16 * i;
        float bias = b_ih[g] + b_hh[g];
        float4 o; float lo, hi;
        unpack2(acc2[i * 2 + 0], lo, hi); o.x = lo + bias; o.y = hi + bias;
        unpack2(acc2[i * 2 + 1], lo, hi); o.z = lo + bias; o.w = hi + bias;
        *(float4*)&g_xproj[((size_t)t * G4_ + g) * B_ + bg * 4] = o;
    }
}

// ---------------- Phase 2: persistent recurrence ------------------------------
// 128 blocks x 512 threads. W_hh slice lives in REGISTERS (64 floats/thread).
// Warp w: rg=w>>2 (rows rg+4i), bg=w&3 (b=bg*8+j). Lane = k-slice (k=lane+32kc).
// Barrier: release/acquire flag array (no sc fences).
extern "C" __global__ void __launch_bounds__(512, 1) lstm_rec_kernel(
    const float* __restrict__ h0,
    const float* __restrict__ c0,
    const float* __restrict__ W_hh,
    float* __restrict__ out)
{
    extern __shared__ float smem[];
    float* hsm  = smem;                        // [512][HS_]  ([k][b])
    float* gacc = hsm + 512 * HS_;             // [16][GA_]
    float* csm  = gacc + 16 * GA_;             // [4][32]

    const int tid  = threadIdx.x;
    const int bid  = blockIdx.x;
    const int w    = tid >> 5;
    const int lane = tid & 31;
    const int rg   = w >> 2;
    const int bg   = w & 3;

    // ---- W_hh slice into registers: wreg[i*16+kc] = W[row rg+4i][lane+32kc] ----
    float wreg[64];
#pragma unroll
    for (int i = 0; i < 4; i++) {
        const int r  = rg + 4 * i;
        const int gt = r >> 2, jl = r & 3;
        const float* wrow = &W_hh[(size_t)(gt * H_ + bid * 4 + jl) * H_];
#pragma unroll
        for (int kc = 0; kc < 16; kc++)
            wreg[i * 16 + kc] = wrow[lane + 32 * kc];
    }
    if (tid < 128) {
        int bb = tid & 31, jl = tid >> 5;
        csm[tid] = c0[bb * H_ + bid * 4 + jl];
    }
    const unsigned epoch = *((volatile unsigned*)&g_epoch);
    const unsigned base  = epoch * 4096u;

    const int r_out = rg + 4 * (lane >> 3);
    const int b_out = bg * 8 + (lane & 7);
    const int gate_out = r_out >> 2, jl_out = r_out & 3;
    const float* xp_base =
        &g_xproj[(size_t)(gate_out * H_ + bid * 4 + jl_out) * B_ + b_out];
    __syncthreads();

    for (int t = 0; t < T_; t++) {
        // ---- stage h into hsm[k][b] ----
        if (t == 0) {
#pragma unroll 4
            for (int m = 0; m < 32; m++) {
                int idx = m * 512 + tid;               // h0 is [b][k]
                int b = idx >> 9, k = idx & 511;
                hsm[k * HS_ + b] = h0[idx];
            }
        } else {
            const float* hsrc = g_h[(t - 1) & 1];      // [k][b] flat
#pragma unroll
            for (int m = 0; m < 8; m++) {
                int f4 = m * 512 + tid;
                float4 v = __ldcg((const float4*)(hsrc) + f4);
                int k = f4 >> 3, b = (f4 & 7) * 4;
                hsm[k * HS_ + b + 0] = v.x;
                hsm[k * HS_ + b + 1] = v.y;
                hsm[k * HS_ + b + 2] = v.z;
                hsm[k * HS_ + b + 3] = v.w;
            }
        }
        float xp = __ldcg(xp_base + (size_t)t * (G4_ * B_));
        __syncthreads();

        // ---- GEMM over this lane's k-slice (W from registers) ----
        unsigned long long acc2[16];
#pragma unroll
        for (int q = 0; q < 16; q++) acc2[q] = 0ull;

#pragma unroll
        for (int kc = 0; kc < 16; kc++) {
            const int k = lane + 32 * kc;
            const float* hb = &hsm[k * HS_ + bg * 8];
            unsigned long long h2[4];
#pragma unroll
            for (int jp = 0; jp < 4; jp++) h2[jp] = pack2(hb[2 * jp], hb[2 * jp + 1]);
#pragma unroll
            for (int i = 0; i < 4; i++) {
                const float wv = wreg[i * 16 + kc];
                unsigned long long w2 = pack2(wv, wv);
#pragma unroll
                for (int jp = 0; jp < 4; jp++) fma2(acc2[i * 4 + jp], w2, h2[jp]);
            }
        }

        float v[32];
#pragma unroll
        for (int i = 0; i < 4; i++)
#pragma unroll
            for (int jp = 0; jp < 4; jp++) {
                float lo, hi;
                unpack2(acc2[i * 4 + jp], lo, hi);
                v[i * 8 + 2 * jp]     = lo;
                v[i * 8 + 2 * jp + 1] = hi;
            }

        // ---- compacted butterfly reduce: lane ends holding sum of v[lane] ----
#pragma unroll
        for (int s = 0; s < 16; s++) {
            float ta = __shfl_xor_sync(0xffffffffu, v[s], 16);
            float tb = __shfl_xor_sync(0xffffffffu, v[s + 16], 16);
            v[s] = (lane & 16) ? (v[s + 16] + tb) : (v[s] + ta);
        }
#pragma unroll
        for (int s = 0; s < 8; s++) {
            float ta = __shfl_xor_sync(0xffffffffu, v[s], 8);
            float tb = __shfl_xor_sync(0xffffffffu, v[s + 8], 8);
            v[s] = (lane & 8) ? (v[s + 8] + tb) : (v[s] + ta);
        }
#pragma unroll
        for (int s = 0; s < 4; s++) {
            float ta = __shfl_xor_sync(0xffffffffu, v[s], 4);
            float tb = __shfl_xor_sync(0xffffffffu, v[s + 4], 4);
            v[s] = (lane & 4) ? (v[s + 4] + tb) : (v[s] + ta);
        }
#pragma unroll
        for (int s = 0; s < 2; s++) {
            float ta = __shfl_xor_sync(0xffffffffu, v[s], 2);
            float tb = __shfl_xor_sync(0xffffffffu, v[s + 2], 2);
            v[s] = (lane & 2) ? (v[s + 2] + tb) : (v[s] + ta);
        }
        {
            float ta = __shfl_xor_sync(0xffffffffu, v[0], 1);
            float tb = __shfl_xor_sync(0xffffffffu, v[1], 1);
            v[0] = (lane & 1) ? (v[1] + tb) : (v[0] + ta);
        }
        gacc[r_out * GA_ + b_out] = v[0] + xp;
        __syncthreads();

        // ---- activations + state update (tanh.approx fast path) ----
        if (tid < 128) {
            int bb = tid & 31, jl = tid >> 5;
            float xi = gacc[(0 * 4 + jl) * GA_ + bb];
            float xf = gacc[(1 * 4 + jl) * GA_ + bb];
            float xg = gacc[(2 * 4 + jl) * GA_ + bb];
            float xo = gacc[(3 * 4 + jl) * GA_ + bb];
            float iv = sigmoid_fast(xi);
            float fv = sigmoid_fast(xf);
            float gv = tanh_approx(xg);
            float ov = sigmoid_fast(xo);
            float c  = csm[tid];
            float cn = fv * c + iv * gv;
            float hn = ov * tanh_approx(cn);
            csm[tid] = cn;
            int j = bid * 4 + jl;
            __stcg(&g_h[t & 1][j * B_ + bb], hn);      // [j][b]
            if (t == T_ - 1) {
                out[bb * H_ + j]           = hn;       // final h [b][j]
                out[B_ * H_ + bb * H_ + j] = cn;       // final c [b][j]
            }
        }
        __syncthreads();   // publishes h stores cta-wide before the release

        // ---- grid barrier: release/acquire flags (no sc fences) ----
        const unsigned target = base + (unsigned)t + 1u;
        if (tid == 0) st_rel(&g_flags[bid], target);
        if (tid < NBLK) {
            while (ld_acq(&g_flags[tid]) < target) { }
        }
        __syncthreads();
    }
}

// ---------------- launch ------------------------------------------------------
extern "C" void kernel_launch(void* const* d_in, const int* in_sizes, int n_in,
                              void* d_out, int out_size)
{
    const float* input = (const float*)d_in[0];
    const float* h0    = (const float*)d_in[1];
    const float* c0    = (const float*)d_in[2];
    const float* W_ih  = (const float*)d_in[3];
    const float* W_hh  = (const float*)d_in[4];
    const float* b_ih  = (const float*)d_in[5];
    const float* b_hh  = (const float*)d_in[6];
    float* out = (float*)d_out;

    dim3 grid1(T_, 16);
    lstm_xproj_kernel<<<grid1, 128>>>(input, W_ih, b_ih, b_hh);

    lstm_epoch_kernel<<<1, 1>>>();

    const int smem_bytes = (512 * HS_ + 16 * GA_ + 128) * sizeof(float);
    cudaFuncSetAttribute(lstm_rec_kernel,
                         cudaFuncAttributeMaxDynamicSharedMemorySize, smem_bytes);
    lstm_rec_kernel<<<NBLK, 512, smem_bytes>>>(h0, c0, W_hh, out);
}

// round 6
// speedup vs baseline: 3.0355x; 2.0621x over previous
#include <cuda_runtime.h>
#include <math.h>
#include <stdint.h>

#define B_   32
#define T_   2048
#define D_   512
#define H_   512
#define G4_  2048
#define NBLK 128
#define XS_  34
#define HSK  516        // hsm row stride (floats); 516 mod 32 = 4

// ---------------- device scratch ----------------------------------------------
__device__ float g_xproj[(size_t)T_ * G4_ * B_];   // [t][g][b]
__device__ __align__(16) float g_h[2][B_ * H_];    // [b][j]  double-buffered
__device__ unsigned g_epoch;
__device__ unsigned g_flags[NBLK * 64];            // one flag per 256B line

// ---------------- helpers -------------------------------------------------------
__device__ __forceinline__ unsigned long long pack2(float lo, float hi) {
    unsigned long long r;
    asm("mov.b64 %0, {%1, %2};" : "=l"(r) : "f"(lo), "f"(hi));
    return r;
}
__device__ __forceinline__ void fma2(unsigned long long& d,
                                     unsigned long long a, unsigned long long b) {
    asm("fma.rn.f32x2 %0, %1, %2, %0;" : "+l"(d) : "l"(a), "l"(b));
}
__device__ __forceinline__ void unpack2(unsigned long long v, float& lo, float& hi) {
    asm("mov.b64 {%0, %1}, %2;" : "=f"(lo), "=f"(hi) : "l"(v));
}
__device__ __forceinline__ unsigned ld_acq(const unsigned* p) {
    unsigned v;
    asm volatile("ld.acquire.gpu.u32 %0, [%1];" : "=r"(v) : "l"(p) : "memory");
    return v;
}
__device__ __forceinline__ void st_rel(unsigned* p, unsigned v) {
    asm volatile("st.release.gpu.u32 [%0], %1;" :: "l"(p), "r"(v) : "memory");
}
__device__ __forceinline__ float tanh_approx(float x) {
    float y;
    asm("tanh.approx.f32 %0, %1;" : "=f"(y) : "f"(x));
    return y;
}
__device__ __forceinline__ float sigmoid_fast(float x) {
    return fmaf(tanh_approx(0.5f * x), 0.5f, 0.5f);
}

__global__ void lstm_epoch_kernel() {
    if (threadIdx.x == 0) g_epoch = g_epoch + 1u;
}

// ---------------- Phase 1: x_proj (unchanged) ----------------------------------
__global__ void __launch_bounds__(128, 4) lstm_xproj_kernel(
    const float* __restrict__ input,
    const float* __restrict__ W_ih,
    const float* __restrict__ b_ih,
    const float* __restrict__ b_hh)
{
    __shared__ float ws[128 * 36];
    __shared__ float xs[32 * XS_];

    const int t   = blockIdx.x;
    const int g0  = blockIdx.y * 128;
    const int tid = threadIdx.x;
    const int gg  = tid >> 3;
    const int bg  = tid & 7;

    unsigned long long acc2[16];
#pragma unroll
    for (int v = 0; v < 16; v++) acc2[v] = 0ull;

    for (int kt = 0; kt < 16; kt++) {
        const int k0 = kt * 32;
#pragma unroll
        for (int m = 0; m < 8; m++) {
            int f4 = tid + m * 128;
            int g = f4 >> 3, kq = f4 & 7;
            float4 v = *(const float4*)&W_ih[(size_t)(g0 + g) * D_ + k0 + kq * 4];
            *(float4*)&ws[g * 36 + kq * 4] = v;
        }
#pragma unroll
        for (int m = 0; m < 2; m++) {
            int f4 = tid + m * 128;
            int b = f4 >> 3, kq = f4 & 7;
            float4 v = *(const float4*)&input[((size_t)b * T_ + t) * D_ + k0 + kq * 4];
            xs[(kq * 4 + 0) * XS_ + b] = v.x;
            xs[(kq * 4 + 1) * XS_ + b] = v.y;
            xs[(kq * 4 + 2) * XS_ + b] = v.z;
            xs[(kq * 4 + 3) * XS_ + b] = v.w;
        }
        __syncthreads();

#pragma unroll
        for (int k4 = 0; k4 < 8; k4++) {
            float4 wv[8];
#pragma unroll
            for (int i = 0; i < 8; i++)
                wv[i] = *(const float4*)&ws[(gg + 16 * i) * 36 + k4 * 4];
#pragma unroll
            for (int kk = 0; kk < 4; kk++) {
                const float* xrow = &xs[(k4 * 4 + kk) * XS_ + bg * 4];
                unsigned long long x2a = *(const unsigned long long*)(xrow);
                unsigned long long x2b = *(const unsigned long long*)(xrow + 2);
#pragma unroll
                for (int i = 0; i < 8; i++) {
                    float w = (kk == 0) ? wv[i].x : (kk == 1) ? wv[i].y
                             : (kk == 2) ? wv[i].z : wv[i].w;
                    unsigned long long w2 = pack2(w, w);
                    fma2(acc2[i * 2 + 0], w2, x2a);
                    fma2(acc2[i * 2 + 1], w2, x2b);
                }
            }
        }
        __syncthreads();
    }

#pragma unroll
    for (int i = 0; i < 8; i++) {
        int g = g0 + gg + 16 * i;
        float bias = b_ih[g] + b_hh[g];
        float4 o; float lo, hi;
        unpack2(acc2[i * 2 + 0], lo, hi); o.x = lo + bias; o.y = hi + bias;
        unpack2(acc2[i * 2 + 1], lo, hi); o.z = lo + bias; o.w = hi + bias;
        *(float4*)&g_xproj[((size_t)t * G4_ + g) * B_ + bg * 4] = o;
    }
}

// ---------------- Phase 2: persistent recurrence (batch-split chains) ----------
// 128 blocks = 32 j-groups x 4 b-groups. Block (jg=bid>>2, bg=bid&3) computes
// gates for j = jg*16..+15, b = bg*8..+7 (all 4 gates). Chains over bg are
// independent: barrier only spans the 32 blocks sharing bg.
// Warp w (0..15) = local j (jl). Lane: GEMM k-slice k=lane+32kc; after the
// reduce, lane L holds gate L>>3 for batch L&7. c lives in lane registers.
extern "C" __global__ void __launch_bounds__(512, 1) lstm_rec_kernel(
    const float* __restrict__ h0,
    const float* __restrict__ c0,
    const float* __restrict__ W_hh,
    float* __restrict__ out)
{
    extern __shared__ float smem[];
    float* hsm = smem;                         // [8][HSK]  ([b_local][k])

    const int tid  = threadIdx.x;
    const int bid  = blockIdx.x;
    const int jg   = bid >> 2;
    const int bg   = bid & 3;
    const int w    = tid >> 5;                 // jl
    const int lane = tid & 31;
    const int j    = jg * 16 + w;

    // ---- W_hh rows (4 gates of row j) into registers ----
    float wreg[64];
#pragma unroll
    for (int i = 0; i < 4; i++) {
        const float* wrow = &W_hh[(size_t)(i * H_ + j) * H_];
#pragma unroll
        for (int kc = 0; kc < 16; kc++)
            wreg[i * 16 + kc] = wrow[lane + 32 * kc];
    }

    // ---- c in registers (lanes 0..7 meaningful) ----
    const int b_mine = bg * 8 + (lane & 7);
    float creg = c0[(size_t)b_mine * H_ + j];

    const unsigned epoch = *((volatile unsigned*)&g_epoch);
    const unsigned base  = epoch * 4096u;

    // per-lane xproj pointer: gate = lane>>3, batch = b_mine
    const float* xp_base =
        &g_xproj[(size_t)((lane >> 3) * H_ + j) * B_ + b_mine];

    // peer flag this lane polls (32 peers sharing bg), padded 256B apart
    const unsigned* my_peer_flag = &g_flags[((lane * 4) + bg) * 64];
    unsigned* my_flag = &g_flags[bid * 64];

    for (int t = 0; t < T_; t++) {
        // ---- stage h rows bg*8..+7 into hsm[b_local][k] ----
        const float* hsrc =
            ((t == 0) ? h0 : g_h[(t - 1) & 1]) + (size_t)(bg * 8) * H_;
#pragma unroll
        for (int m = 0; m < 2; m++) {
            int f4 = tid + m * 512;
            int bl = f4 >> 7, kq = f4 & 127;
            float4 v = __ldcg((const float4*)(hsrc + bl * H_) + kq);
            *(float4*)&hsm[bl * HSK + kq * 4] = v;
        }
        float xp = __ldcg(xp_base + (size_t)t * (G4_ * B_));
        __syncthreads();

        // ---- GEMM: 16 f32x2 accumulators over this lane's k-slice ----
        unsigned long long acc2[16];
#pragma unroll
        for (int q = 0; q < 16; q++) acc2[q] = 0ull;

#pragma unroll
        for (int kc = 0; kc < 16; kc++) {
            const int k = lane + 32 * kc;
            float hb[8];
#pragma unroll
            for (int bl = 0; bl < 8; bl++) hb[bl] = hsm[bl * HSK + k];
            unsigned long long h2[4];
#pragma unroll
            for (int jp = 0; jp < 4; jp++) h2[jp] = pack2(hb[2 * jp], hb[2 * jp + 1]);
#pragma unroll
            for (int i = 0; i < 4; i++) {
                const float wv = wreg[i * 16 + kc];
                unsigned long long w2 = pack2(wv, wv);
#pragma unroll
                for (int jp = 0; jp < 4; jp++) fma2(acc2[i * 4 + jp], w2, h2[jp]);
            }
        }

        // ---- butterfly reduce, stage-16 folded into the unpack ----
        float v16[16];
#pragma unroll
        for (int i = 0; i < 2; i++)
#pragma unroll
            for (int jp = 0; jp < 4; jp++) {
                float alo, ahi, blo, bhi;
                unpack2(acc2[i * 4 + jp],       alo, ahi);
                unpack2(acc2[(i + 2) * 4 + jp], blo, bhi);
                int s0 = i * 8 + 2 * jp;
                float ta = __shfl_xor_sync(0xffffffffu, alo, 16);
                float tb = __shfl_xor_sync(0xffffffffu, blo, 16);
                v16[s0] = (lane & 16) ? (blo + tb) : (alo + ta);
                ta = __shfl_xor_sync(0xffffffffu, ahi, 16);
                tb = __shfl_xor_sync(0xffffffffu, bhi, 16);
                v16[s0 + 1] = (lane & 16) ? (bhi + tb) : (ahi + ta);
            }
#pragma unroll
        for (int s = 0; s < 8; s++) {
            float ta = __shfl_xor_sync(0xffffffffu, v16[s], 8);
            float tb = __shfl_xor_sync(0xffffffffu, v16[s + 8], 8);
            v16[s] = (lane & 8) ? (v16[s + 8] + tb) : (v16[s] + ta);
        }
#pragma unroll
        for (int s = 0; s < 4; s++) {
            float ta = __shfl_xor_sync(0xffffffffu, v16[s], 4);
            float tb = __shfl_xor_sync(0xffffffffu, v16[s + 4], 4);
            v16[s] = (lane & 4) ? (v16[s + 4] + tb) : (v16[s] + ta);
        }
#pragma unroll
        for (int s = 0; s < 2; s++) {
            float ta = __shfl_xor_sync(0xffffffffu, v16[s], 2);
            float tb = __shfl_xor_sync(0xffffffffu, v16[s + 2], 2);
            v16[s] = (lane & 2) ? (v16[s + 2] + tb) : (v16[s] + ta);
        }
        {
            float ta = __shfl_xor_sync(0xffffffffu, v16[0], 1);
            float tb = __shfl_xor_sync(0xffffffffu, v16[1], 1);
            v16[0] = (lane & 1) ? (v16[1] + tb) : (v16[0] + ta);
        }
        // lane L now holds preact for gate L>>3, batch bg*8+(L&7)
        float pre = v16[0] + xp;

        // ---- in-warp activation: lanes 0..7 gather f/g/o from +8/+16/+24 ----
        float xf = __shfl_down_sync(0xffffffffu, pre, 8);
        float xg = __shfl_down_sync(0xffffffffu, pre, 16);
        float xo = __shfl_down_sync(0xffffffffu, pre, 24);
        float iv = sigmoid_fast(pre);
        float fv = sigmoid_fast(xf);
        float gv = tanh_approx(xg);
        float ov = sigmoid_fast(xo);
        float cn = fv * creg + iv * gv;
        float hn = ov * tanh_approx(cn);
        if (lane < 8) {
            creg = cn;
            __stcg(&g_h[t & 1][(size_t)b_mine * H_ + j], hn);
            if (t == T_ - 1) {
                out[(size_t)b_mine * H_ + j]            = hn;
                out[(size_t)B_ * H_ + b_mine * H_ + j]  = cn;
            }
        }
        __syncthreads();   // all warps' h stores ordered before the release

        // ---- chain barrier: 32 peers sharing bg, padded flags ----
        const unsigned target = base + (unsigned)t + 1u;
        if (tid == 0) st_rel(my_flag, target);
        if (tid < 32) {
            while (ld_acq(my_peer_flag) < target) { }
        }
        __syncthreads();
    }
}

// ---------------- launch ------------------------------------------------------
extern "C" void kernel_launch(void* const* d_in, const int* in_sizes, int n_in,
                              void* d_out, int out_size)
{
    const float* input = (const float*)d_in[0];
    const float* h0    = (const float*)d_in[1];
    const float* c0    = (const float*)d_in[2];
    const float* W_ih  = (const float*)d_in[3];
    const float* W_hh  = (const float*)d_in[4];
    const float* b_ih  = (const float*)d_in[5];
    const float* b_hh  = (const float*)d_in[6];
    float* out = (float*)d_out;

    dim3 grid1(T_, 16);
    lstm_xproj_kernel<<<grid1, 128>>>(input, W_ih, b_ih, b_hh);

    lstm_epoch_kernel<<<1, 1>>>();

    const int smem_bytes = (8 * HSK) * sizeof(float);
    cudaFuncSetAttribute(lstm_rec_kernel,
                         cudaFuncAttributeMaxDynamicSharedMemorySize, smem_bytes);
    lstm_rec_kernel<<<NBLK, 512, smem_bytes>>>(h0, c0, W_hh, out);
}